// round 4
// baseline (speedup 1.0000x reference)
#include <cuda_runtime.h>

// SPU transformer bound propagation: elementwise over N=8192 rows.
// float4 = 2 rows/thread; grid 32 x block 128 = 4096 threads exactly (no guard).
// Fast-math sigmoid (__expf + __fdividef): rel_err ~2.5e-7 << 1e-3 threshold.

__device__ __forceinline__ float2 spu_row(float l, float u,
                                          float ls_l, float ls_u,
                                          float lsh_l, float lsh_u,
                                          float lb_l, float lb_u) {
    // Both EX2s issued adjacently so their MUFU latencies overlap.
    float el = __expf(l);
    float eu = __expf(u);
    float vl_neg = __fdividef(1.0f, 1.0f + el) - 1.0f;
    float vu_neg = __fdividef(1.0f, 1.0f + eu) - 1.0f;
    float vl = (l >= 0.0f) ? fmaf(l, l, -0.5f) : vl_neg;
    float vu = (u >= 0.0f) ? fmaf(u, u, -0.5f) : vu_neg;

    bool neg   = (u <= 0.0f);
    bool pos   = (l >= 0.0f);
    bool cross = !(neg || pos);

    float all_slopes = __fdividef(vu - vl, u - l);
    float slope_u = (pos || cross) ? all_slopes : 0.0f;
    float slope_l = neg ? all_slopes : 0.0f;

    bool sw = (all_slopes < 0.0f);
    float v_l = sw ? vu : vl;
    float v_u = sw ? vl : vu;
    float b_l = sw ? u : l;
    float b_u = sw ? l : u;

    float bnd_l = cross ? -0.5f : v_l;
    float bnd_u = v_u;

    float shift_u = fmaf(-slope_u, b_u, v_u);
    float shift_l = cross ? -0.5f : fmaf(-slope_l, b_l, v_l);

    float Ud = slope_u * ls_u;
    float UV = fmaf(slope_u, lsh_u, shift_u);
    float Ld = slope_l * ls_l;
    float LV = fmaf(slope_l, lsh_l, shift_l);

    float lb = fmaf(fmaxf(Ld, 0.0f), lb_l, fmaf(fminf(Ld, 0.0f), lb_u, LV));
    float ub = fmaf(fmaxf(Ud, 0.0f), lb_u, fmaf(fminf(Ud, 0.0f), lb_l, UV));

    return make_float2(fmaxf(lb, bnd_l), fminf(ub, bnd_u));
}

__global__ void __launch_bounds__(128, 1) spu_transformer_kernel(
    const float4* __restrict__ bounds,
    const float4* __restrict__ last_slopes,
    const float4* __restrict__ last_shifts,
    const float4* __restrict__ last_bounds,
    float4* __restrict__ out)
{
    int i = blockIdx.x * blockDim.x + threadIdx.x;  // exact: 32*128 = 4096 = n4

    float4 b   = bounds[i];
    float4 ls  = last_slopes[i];
    float4 lsh = last_shifts[i];
    float4 lb2 = last_bounds[i];

    float2 r0 = spu_row(b.x, b.y, ls.x, ls.y, lsh.x, lsh.y, lb2.x, lb2.y);
    float2 r1 = spu_row(b.z, b.w, ls.z, ls.w, lsh.z, lsh.w, lb2.z, lb2.w);

    out[i] = make_float4(r0.x, r0.y, r1.x, r1.y);
}

// Fallback with guard for sizes not divisible by 512 floats (safety).
__global__ void spu_transformer_kernel_guard(
    const float4* __restrict__ bounds,
    const float4* __restrict__ last_slopes,
    const float4* __restrict__ last_shifts,
    const float4* __restrict__ last_bounds,
    float4* __restrict__ out,
    int n4)
{
    int i = blockIdx.x * blockDim.x + threadIdx.x;
    if (i >= n4) return;
    float4 b   = bounds[i];
    float4 ls  = last_slopes[i];
    float4 lsh = last_shifts[i];
    float4 lb2 = last_bounds[i];
    float2 r0 = spu_row(b.x, b.y, ls.x, ls.y, lsh.x, lsh.y, lb2.x, lb2.y);
    float2 r1 = spu_row(b.z, b.w, ls.z, ls.w, lsh.z, lsh.w, lb2.z, lb2.w);
    out[i] = make_float4(r0.x, r0.y, r1.x, r1.y);
}

extern "C" void kernel_launch(void* const* d_in, const int* in_sizes, int n_in,
                              void* d_out, int out_size) {
    const float4* bounds      = (const float4*)d_in[0];
    const float4* last_slopes = (const float4*)d_in[1];
    const float4* last_shifts = (const float4*)d_in[2];
    const float4* last_bounds = (const float4*)d_in[3];
    float4* out = (float4*)d_out;

    int n4 = in_sizes[0] / 4;  // 8192*2 floats -> 4096 float4
    const int threads = 128;
    if (n4 % threads == 0) {
        spu_transformer_kernel<<<n4 / threads, threads>>>(
            bounds, last_slopes, last_shifts, last_bounds, out);
    } else {
        spu_transformer_kernel_guard<<<(n4 + threads - 1) / threads, threads>>>(
            bounds, last_slopes, last_shifts, last_bounds, out, n4);
    }
}

// round 5
// speedup vs baseline: 1.0561x; 1.0561x over previous
#include <cuda_runtime.h>

// SPU transformer bound propagation: elementwise over N=8192 rows.
// Best-known config: grid 32 x block 128, float4 = 2 rows/thread, no guard.
// Fast-math sigmoid: sigmoid(-x)-1 = -e^x/(1+e^x), one __expf + one __fdividef.
// rel_err ~2.5e-7, threshold 1e-3.

__device__ __forceinline__ float2 spu_row(float l, float u,
                                          float ls_l, float ls_u,
                                          float lsh_l, float lsh_u,
                                          float lb_l, float lb_u) {
    // Both EX2s adjacent so the two MUFU latencies overlap.
    float el = __expf(l);
    float eu = __expf(u);
    float vl_neg = __fdividef(-el, 1.0f + el);   // = sigmoid(-l) - 1
    float vu_neg = __fdividef(-eu, 1.0f + eu);
    float vl = (l >= 0.0f) ? fmaf(l, l, -0.5f) : vl_neg;
    float vu = (u >= 0.0f) ? fmaf(u, u, -0.5f) : vu_neg;

    bool neg   = (u <= 0.0f);
    bool pos   = (l >= 0.0f);
    bool cross = !(neg || pos);

    float all_slopes = __fdividef(vu - vl, u - l);
    float slope_u = (pos || cross) ? all_slopes : 0.0f;
    float slope_l = neg ? all_slopes : 0.0f;

    bool sw = (all_slopes < 0.0f);
    float v_l = sw ? vu : vl;
    float v_u = sw ? vl : vu;
    float b_l = sw ? u : l;
    float b_u = sw ? l : u;

    float bnd_l = cross ? -0.5f : v_l;
    float bnd_u = v_u;

    float shift_u = fmaf(-slope_u, b_u, v_u);
    float shift_l = cross ? -0.5f : fmaf(-slope_l, b_l, v_l);

    float Ud = slope_u * ls_u;
    float UV = fmaf(slope_u, lsh_u, shift_u);
    float Ld = slope_l * ls_l;
    float LV = fmaf(slope_l, lsh_l, shift_l);

    float lb = fmaf(fmaxf(Ld, 0.0f), lb_l, fmaf(fminf(Ld, 0.0f), lb_u, LV));
    float ub = fmaf(fmaxf(Ud, 0.0f), lb_u, fmaf(fminf(Ud, 0.0f), lb_l, UV));

    return make_float2(fmaxf(lb, bnd_l), fminf(ub, bnd_u));
}

__global__ void __launch_bounds__(128, 1) spu_transformer_kernel(
    const float4* __restrict__ bounds,
    const float4* __restrict__ last_slopes,
    const float4* __restrict__ last_shifts,
    const float4* __restrict__ last_bounds,
    float4* __restrict__ out,
    int n4)
{
    int i = blockIdx.x * blockDim.x + threadIdx.x;
    if (i < n4) {
        float4 b   = bounds[i];
        float4 ls  = last_slopes[i];
        float4 lsh = last_shifts[i];
        float4 lb2 = last_bounds[i];

        float2 r0 = spu_row(b.x, b.y, ls.x, ls.y, lsh.x, lsh.y, lb2.x, lb2.y);
        float2 r1 = spu_row(b.z, b.w, ls.z, ls.w, lsh.z, lsh.w, lb2.z, lb2.w);

        out[i] = make_float4(r0.x, r0.y, r1.x, r1.y);
    }
}

extern "C" void kernel_launch(void* const* d_in, const int* in_sizes, int n_in,
                              void* d_out, int out_size) {
    const float4* bounds      = (const float4*)d_in[0];
    const float4* last_slopes = (const float4*)d_in[1];
    const float4* last_shifts = (const float4*)d_in[2];
    const float4* last_bounds = (const float4*)d_in[3];
    float4* out = (float4*)d_out;

    int n4 = in_sizes[0] / 4;            // 8192*2 floats -> 4096 float4
    const int threads = 128;
    int blocks = (n4 + threads - 1) / threads;  // 32
    spu_transformer_kernel<<<blocks, threads>>>(
        bounds, last_slopes, last_shifts, last_bounds, out, n4);
}